// round 3
// baseline (speedup 1.0000x reference)
#include <cuda_runtime.h>
#include <cstdint>

#define Bsz 1024
#define Tt 64
#define Dd 128
#define Hh 128
#define ATT 64
#define HOR 24
#define G 8
#define NCTAS (Bsz/G)
#define NTHR 512

// ---------------- device scratch (no allocations allowed) ----------------
__device__ float g_WihT[Dd * 4 * Hh];   // [k][o] 128 x 512 (enc_Wih transposed)
__device__ float g_WhhT[Hh * 4 * Hh];   // [k][o] 128 x 512 (enc_Whh transposed)
__device__ float g_WhhTd[Hh * 4 * Hh];  // [k][o] 128 x 512 (dec_Whh transposed)
__device__ float g_hid[(size_t)Bsz * Tt * Hh];   // encoder hiddens [b][t][h]
__device__ float g_proj[(size_t)Bsz * ATT * Tt]; // enc_proj transposed [b][a][t]

// ---------------- helpers ----------------
__device__ __forceinline__ float tanh_fast(float x) {
    float y; asm("tanh.approx.f32 %0, %1;" : "=f"(y) : "f"(x)); return y;
}
__device__ __forceinline__ float sigm(float x) {
    return 1.f / (1.f + __expf(-x));
}
__device__ __forceinline__ float tanh_acc(float x) {
    float ax = fabsf(x);
    float e = __expf(-2.f * ax);
    float t = (1.f - e) / (1.f + e);
    return copysignf(t, x);
}

// ---------------- prologue: transpose LSTM weight matrices ----------------
__global__ void transpose_k(const float* __restrict__ Wih,
                            const float* __restrict__ Whh,
                            const float* __restrict__ Wdh) {
    int i = blockIdx.x * blockDim.x + threadIdx.x;
    if (i < 512 * 128) {
        int o = i >> 7, k = i & 127;    // source row-major (512,128)
        g_WihT[k * 512 + o]  = Wih[i];
        g_WhhT[k * 512 + o]  = Whh[i];
        g_WhhTd[k * 512 + o] = Wdh[i];
    }
}

// smem float counts
#define OFF_W      0
#define SZ_W       24640              // 64*385 (holds We_w@257 or Wd_w@385)
#define OFF_H      (OFF_W + SZ_W)
#define OFF_C      (OFF_H + 1024)
#define OFF_X      (OFF_C + 1024)
#define OFF_BASE   (OFF_X + 1024)
#define OFF_SC     (OFF_BASE + 512)
#define OFF_GATES  (OFF_SC + 1024)
#define OFF_BIAS   (OFF_GATES + 4096)
#define OFF_WEB    (OFF_BIAS + 512)
#define OFF_VEW    (OFF_WEB + 64)
#define OFF_WDB    (OFF_VEW + 64)
#define OFF_VDW    (OFF_WDB + 64)
#define OFF_DWIH   (OFF_VDW + 64)
#define OFF_FCW    (OFF_DWIH + 512)
#define OFF_YH     (OFF_FCW + 320)
#define OFF_RED    (OFF_YH + 512)
#define OFF_RED2   (OFF_RED + 16)
#define OFF_YPREV  (OFF_RED2 + 16)
#define SMEM_FLOATS (OFF_YPREV + 8)
#define SMEM_BYTES  (SMEM_FLOATS * 4)

__global__ void __launch_bounds__(NTHR, 1)
darnn_kernel(const float* __restrict__ X,        const float* __restrict__ y_hist,
             const float* __restrict__ We_w,     const float* __restrict__ We_b,
             const float* __restrict__ ve_w,     const float* __restrict__ ve_b,
             const float* __restrict__ enc_bih,  const float* __restrict__ enc_bhh,
             const float* __restrict__ dec_Wih,  const float* __restrict__ dec_bih,
             const float* __restrict__ dec_bhh,
             const float* __restrict__ Wd_w,     const float* __restrict__ Wd_b,
             const float* __restrict__ vd_w,     const float* __restrict__ vd_b,
             const float* __restrict__ fc_w,     const float* __restrict__ fc_b,
             float* __restrict__ out) {
    extern __shared__ float sm[];
    float* sW      = sm + OFF_W;
    float* s_h     = sm + OFF_H;
    float* s_c     = sm + OFF_C;
    float* s_x     = sm + OFF_X;      // x_t / x_tilde / hid-stage / context
    float* s_base  = sm + OFF_BASE;
    float* s_sc    = sm + OFF_SC;     // beta in decoder
    float* s_gates = sm + OFF_GATES;
    float* s_bias  = sm + OFF_BIAS;
    float* s_Web   = sm + OFF_WEB;
    float* s_vew   = sm + OFF_VEW;
    float* s_Wdb   = sm + OFF_WDB;
    float* s_vdw   = sm + OFF_VDW;
    float* s_dWih  = sm + OFF_DWIH;
    float* s_fcw   = sm + OFF_FCW;
    float* s_yh    = sm + OFF_YH;
    float* s_red   = sm + OFF_RED;
    float* s_red2  = sm + OFF_RED2;
    float* s_yprev = sm + OFF_YPREV;

    const int tid  = threadIdx.x;
    const int lane = tid & 31;
    const int wrp  = tid >> 5;
    const int b0   = blockIdx.x * G;

    const float ve_b_r = ve_b[0];

    // ---------- preload (encoder) ----------
    for (int i = tid; i < 64 * 257; i += NTHR) sW[i] = We_w[i];   // stride 257 kept
    if (tid < 512) s_bias[tid] = enc_bih[tid] + enc_bhh[tid];
    if (tid < 64) { s_Web[tid] = We_b[tid]; s_vew[tid] = ve_w[tid]; }
    if (tid < G * Tt) s_yh[tid] = y_hist[b0 * Tt + tid];
    if (tid < G * Hh) { s_h[tid] = 0.f; s_c[tid] = 0.f; }
    if (tid + NTHR < G * Hh) { s_h[tid + NTHR] = 0.f; s_c[tid + NTHR] = 0.f; }
    __syncthreads();

    const float4* WihT4  = reinterpret_cast<const float4*>(g_WihT);
    const float4* WhhT4  = reinterpret_cast<const float4*>(g_WhhT);
    const float4* WhhTd4 = reinterpret_cast<const float4*>(g_WhhTd);
    float4* s_gates4 = reinterpret_cast<float4*>(s_gates);

    // ================= ENCODER: 64 steps =================
    for (int t = 0; t < Tt; ++t) {
        // E1: load x_t into smem [g][d]
        {
            const float* Xp = X + (size_t)b0 * Tt * Dd + (size_t)t * Dd;
            int i = tid;
            s_x[i] = Xp[(i >> 7) * Tt * Dd + (i & 127)];
            i = tid + NTHR;
            s_x[i] = Xp[(i >> 7) * Tt * Dd + (i & 127)];
        }
        // E2: base[g][a] = We_b[a] + h·Whs[a,:128] + c·Whs[a,128:256]
        {
            int g = tid >> 6, a = tid & 63;
            const float* Wr = sW + a * 257;
            const float* hg = s_h + g * 128;
            const float* cg = s_c + g * 128;
            float acc = s_Web[a];
            #pragma unroll 8
            for (int j = 0; j < 128; ++j) acc = fmaf(hg[j], Wr[j], acc);
            #pragma unroll 8
            for (int j = 0; j < 128; ++j) acc = fmaf(cg[j], Wr[128 + j], acc);
            s_base[tid] = acc;
        }
        __syncthreads();
        // E3+E4: scores, softmax over D, x_tilde (in place)
        {
            int g = tid >> 6, d0 = tid & 63;
            float x1 = s_x[g * 128 + d0];
            float x2 = s_x[g * 128 + d0 + 64];
            float a1 = ve_b_r, a2 = ve_b_r;
            const float* bg = s_base + g * 64;
            #pragma unroll 4
            for (int a = 0; a < 64; ++a) {
                float ba = bg[a];
                float wf = sW[a * 257 + 256];
                float vw = s_vew[a];
                a1 = fmaf(vw, tanh_fast(fmaf(x1, wf, ba)), a1);
                a2 = fmaf(vw, tanh_fast(fmaf(x2, wf, ba)), a2);
            }
            float m = fmaxf(a1, a2);
            #pragma unroll
            for (int o = 16; o; o >>= 1) m = fmaxf(m, __shfl_xor_sync(0xffffffffu, m, o));
            if (lane == 0) s_red[wrp] = m;
            __syncthreads();
            float gm = fmaxf(s_red[2 * g], s_red[2 * g + 1]);
            float e1 = __expf(a1 - gm), e2 = __expf(a2 - gm);
            float ss = e1 + e2;
            #pragma unroll
            for (int o = 16; o; o >>= 1) ss += __shfl_xor_sync(0xffffffffu, ss, o);
            if (lane == 0) s_red2[wrp] = ss;
            __syncthreads();
            float inv = 1.f / (s_red2[2 * g] + s_red2[2 * g + 1]);
            s_x[g * 128 + d0]      = x1 * e1 * inv;
            s_x[g * 128 + d0 + 64] = x2 * e2 * inv;
        }
        __syncthreads();
        // E5: gates[g][o] = bias + x_tilde·Wih^T + h·Whh^T
        {
            int gg = tid >> 7, og = tid & 127;
            int g0 = gg * 2, g1 = g0 + 1;
            int o0 = og * 4;
            float a00 = s_bias[o0 + 0], a10 = s_bias[o0 + 1];
            float a20 = s_bias[o0 + 2], a30 = s_bias[o0 + 3];
            float a01 = a00, a11 = a10, a21 = a20, a31 = a30;
            const float* xa = s_x + g0 * 128;
            const float* xb = s_x + g1 * 128;
            const float* ha = s_h + g0 * 128;
            const float* hb = s_h + g1 * 128;
            #pragma unroll 4
            for (int k = 0; k < 128; ++k) {
                float4 w = __ldg(&WihT4[k * 128 + og]);
                float va = xa[k], vb = xb[k];
                a00 = fmaf(w.x, va, a00); a01 = fmaf(w.x, vb, a01);
                a10 = fmaf(w.y, va, a10); a11 = fmaf(w.y, vb, a11);
                a20 = fmaf(w.z, va, a20); a21 = fmaf(w.z, vb, a21);
                a30 = fmaf(w.w, va, a30); a31 = fmaf(w.w, vb, a31);
            }
            #pragma unroll 4
            for (int k = 0; k < 128; ++k) {
                float4 w = __ldg(&WhhT4[k * 128 + og]);
                float va = ha[k], vb = hb[k];
                a00 = fmaf(w.x, va, a00); a01 = fmaf(w.x, vb, a01);
                a10 = fmaf(w.y, va, a10); a11 = fmaf(w.y, vb, a11);
                a20 = fmaf(w.z, va, a20); a21 = fmaf(w.z, vb, a21);
                a30 = fmaf(w.w, va, a30); a31 = fmaf(w.w, vb, a31);
            }
            s_gates4[g0 * 128 + og] = make_float4(a00, a10, a20, a30);
            s_gates4[g1 * 128 + og] = make_float4(a01, a11, a21, a31);
        }
        __syncthreads();
        // E6: LSTM cell update, store h2 to global hiddens
        {
            int u = tid & 127, gb = tid >> 7;
            #pragma unroll
            for (int q = 0; q < 2; ++q) {
                int g = gb + q * 4;
                const float* gr = s_gates + g * 512;
                float ig = sigm(gr[u]);
                float fg = sigm(gr[128 + u]);
                float gv = tanh_acc(gr[256 + u]);
                float ov = sigm(gr[384 + u]);
                float c2 = fmaf(fg, s_c[g * 128 + u], ig * gv);
                float h2 = ov * tanh_acc(c2);
                s_c[g * 128 + u] = c2;
                s_h[g * 128 + u] = h2;
                g_hid[((size_t)(b0 + g)) * Tt * Hh + (size_t)t * Hh + u] = h2;
            }
        }
        __syncthreads();
    }

    // ================= enc_proj: proj[b][a][t] = hid[b][t][:]·Wd_w[a,:128] =================
    for (int i = tid; i < 64 * 384; i += NTHR) {
        int r = i / 384, cc = i - r * 384;
        sW[r * 385 + cc] = Wd_w[i];
    }
    __syncthreads();
    for (int t = 0; t < Tt; ++t) {
        {
            const float* hp = g_hid + (size_t)b0 * Tt * Hh + (size_t)t * Hh;
            int i = tid;
            s_x[i] = hp[(i >> 7) * Tt * Hh + (i & 127)];
            i = tid + NTHR;
            s_x[i] = hp[(i >> 7) * Tt * Hh + (i & 127)];
        }
        __syncthreads();
        {
            int g = tid >> 6, a = tid & 63;
            const float* Wr = sW + a * 385;
            const float* hg = s_x + g * 128;
            float acc = 0.f;
            #pragma unroll 8
            for (int j = 0; j < 128; ++j) acc = fmaf(hg[j], Wr[j], acc);
            g_proj[((size_t)(b0 + g)) * ATT * Tt + a * Tt + t] = acc;
        }
        __syncthreads();
    }

    // ---------- preload (decoder) ----------
    if (tid < 512) {
        s_bias[tid] = dec_bih[tid] + dec_bhh[tid];
        s_dWih[tid] = dec_Wih[tid];
    }
    if (tid < 64) { s_Wdb[tid] = Wd_b[tid]; s_vdw[tid] = vd_w[tid]; }
    if (tid < 320) s_fcw[tid] = fc_w[tid];
    if (tid < G * Hh) { s_h[tid] = 0.f; s_c[tid] = 0.f; }
    if (tid + NTHR < G * Hh) { s_h[tid + NTHR] = 0.f; s_c[tid + NTHR] = 0.f; }
    if (tid < G) s_yprev[tid] = s_yh[tid * Tt + Tt - 1];
    const float vd_b_r = vd_b[0];
    const float fc_b_r = fc_b[0];
    __syncthreads();

    // ================= DECODER: 24 steps =================
    for (int s = 0; s < HOR; ++s) {
        // D1: dc[g][a]
        {
            int g = tid >> 6, a = tid & 63;
            const float* Wr = sW + a * 385;
            const float* dg = s_h + g * 128;
            const float* cg = s_c + g * 128;
            float acc = s_Wdb[a];
            #pragma unroll 8
            for (int j = 0; j < 128; ++j) acc = fmaf(dg[j], Wr[128 + j], acc);
            #pragma unroll 8
            for (int j = 0; j < 128; ++j) acc = fmaf(cg[j], Wr[256 + j], acc);
            s_base[tid] = acc;
        }
        __syncthreads();
        // D2+D3: temporal scores + softmax -> beta in s_sc
        {
            int g = tid >> 6, tt = tid & 63;
            const float* pp = g_proj + ((size_t)(b0 + g)) * ATT * Tt + tt;
            const float* bg = s_base + g * 64;
            float acc = vd_b_r;
            #pragma unroll 4
            for (int a = 0; a < 64; ++a)
                acc = fmaf(s_vdw[a], tanh_fast(pp[a * 64] + bg[a]), acc);
            float m = acc;
            #pragma unroll
            for (int o = 16; o; o >>= 1) m = fmaxf(m, __shfl_xor_sync(0xffffffffu, m, o));
            if (lane == 0) s_red[wrp] = m;
            __syncthreads();
            float gm = fmaxf(s_red[2 * g], s_red[2 * g + 1]);
            float e = __expf(acc - gm);
            float ssum = e;
            #pragma unroll
            for (int o = 16; o; o >>= 1) ssum += __shfl_xor_sync(0xffffffffu, ssum, o);
            if (lane == 0) s_red2[wrp] = ssum;
            __syncthreads();
            float inv = 1.f / (s_red2[2 * g] + s_red2[2 * g + 1]);
            s_sc[g * 64 + tt] = e * inv;
        }
        __syncthreads();
        // D4: context[g][u] -> s_x
        {
            int u = tid & 127, gb = tid >> 7;
            #pragma unroll
            for (int q = 0; q < 2; ++q) {
                int g = gb + q * 4;
                const float* hp = g_hid + ((size_t)(b0 + g)) * Tt * Hh + u;
                const float* be = s_sc + g * 64;
                float acc = 0.f;
                #pragma unroll 8
                for (int tt = 0; tt < 64; ++tt) acc = fmaf(be[tt], hp[tt * 128], acc);
                s_x[g * 128 + u] = acc;
            }
        }
        __syncthreads();
        // D5: decoder LSTM gates (input is scalar y_prev)
        {
            int gg = tid >> 7, og = tid & 127;
            int g0 = gg * 2, g1 = g0 + 1;
            int o0 = og * 4;
            float y0 = s_yprev[g0], y1 = s_yprev[g1];
            float a00 = fmaf(s_dWih[o0 + 0], y0, s_bias[o0 + 0]);
            float a10 = fmaf(s_dWih[o0 + 1], y0, s_bias[o0 + 1]);
            float a20 = fmaf(s_dWih[o0 + 2], y0, s_bias[o0 + 2]);
            float a30 = fmaf(s_dWih[o0 + 3], y0, s_bias[o0 + 3]);
            float a01 = fmaf(s_dWih[o0 + 0], y1, s_bias[o0 + 0]);
            float a11 = fmaf(s_dWih[o0 + 1], y1, s_bias[o0 + 1]);
            float a21 = fmaf(s_dWih[o0 + 2], y1, s_bias[o0 + 2]);
            float a31 = fmaf(s_dWih[o0 + 3], y1, s_bias[o0 + 3]);
            const float* ha = s_h + g0 * 128;
            const float* hb = s_h + g1 * 128;
            #pragma unroll 4
            for (int k = 0; k < 128; ++k) {
                float4 w = __ldg(&WhhTd4[k * 128 + og]);
                float va = ha[k], vb = hb[k];
                a00 = fmaf(w.x, va, a00); a01 = fmaf(w.x, vb, a01);
                a10 = fmaf(w.y, va, a10); a11 = fmaf(w.y, vb, a11);
                a20 = fmaf(w.z, va, a20); a21 = fmaf(w.z, vb, a21);
                a30 = fmaf(w.w, va, a30); a31 = fmaf(w.w, vb, a31);
            }
            s_gates4[g0 * 128 + og] = make_float4(a00, a10, a20, a30);
            s_gates4[g1 * 128 + og] = make_float4(a01, a11, a21, a31);
        }
        __syncthreads();
        // D6: LSTM update (d2 in s_h)
        {
            int u = tid & 127, gb = tid >> 7;
            #pragma unroll
            for (int q = 0; q < 2; ++q) {
                int g = gb + q * 4;
                const float* gr = s_gates + g * 512;
                float ig = sigm(gr[u]);
                float fg = sigm(gr[128 + u]);
                float gv = tanh_acc(gr[256 + u]);
                float ov = sigm(gr[384 + u]);
                float c2 = fmaf(fg, s_c[g * 128 + u], ig * gv);
                float h2 = ov * tanh_acc(c2);
                s_c[g * 128 + u] = c2;
                s_h[g * 128 + u] = h2;
            }
        }
        __syncthreads();
        // D7: fc  out = fc_b + fc_w · [d2, context, y_hist]
        if (wrp < G) {
            int g = wrp;
            float acc = 0.f;
            for (int idx = lane; idx < 320; idx += 32) {
                float v;
                if (idx < 128)       v = s_h[g * 128 + idx];
                else if (idx < 256)  v = s_x[g * 128 + idx - 128];
                else                 v = s_yh[g * 64 + idx - 256];
                acc = fmaf(s_fcw[idx], v, acc);
            }
            #pragma unroll
            for (int o = 16; o; o >>= 1) acc += __shfl_xor_sync(0xffffffffu, acc, o);
            if (lane == 0) {
                float ov = acc + fc_b_r;
                s_yprev[g] = ov;
                out[(b0 + g) * HOR + s] = ov;
            }
        }
        __syncthreads();
    }
}

extern "C" void kernel_launch(void* const* d_in, const int* in_sizes, int n_in,
                              void* d_out, int out_size) {
    const float* X        = (const float*)d_in[0];
    const float* y_hist   = (const float*)d_in[1];
    const float* We_w     = (const float*)d_in[2];
    const float* We_b     = (const float*)d_in[3];
    const float* ve_w     = (const float*)d_in[4];
    const float* ve_b     = (const float*)d_in[5];
    const float* enc_Wih  = (const float*)d_in[6];
    const float* enc_Whh  = (const float*)d_in[7];
    const float* enc_bih  = (const float*)d_in[8];
    const float* enc_bhh  = (const float*)d_in[9];
    const float* dec_Wih  = (const float*)d_in[10];
    const float* dec_Whh  = (const float*)d_in[11];
    const float* dec_bih  = (const float*)d_in[12];
    const float* dec_bhh  = (const float*)d_in[13];
    const float* Wd_w     = (const float*)d_in[14];
    const float* Wd_b     = (const float*)d_in[15];
    const float* vd_w     = (const float*)d_in[16];
    const float* vd_b     = (const float*)d_in[17];
    const float* fc_w     = (const float*)d_in[18];
    const float* fc_b     = (const float*)d_in[19];
    float* out = (float*)d_out;

    cudaFuncSetAttribute(darnn_kernel,
                         cudaFuncAttributeMaxDynamicSharedMemorySize, SMEM_BYTES);

    transpose_k<<<(512 * 128 + 255) / 256, 256>>>(enc_Wih, enc_Whh, dec_Whh);
    darnn_kernel<<<NCTAS, NTHR, SMEM_BYTES>>>(
        X, y_hist, We_w, We_b, ve_w, ve_b,
        enc_bih, enc_bhh, dec_Wih, dec_bih, dec_bhh,
        Wd_w, Wd_b, vd_w, vd_b, fc_w, fc_b, out);
}

// round 4
// speedup vs baseline: 1.0562x; 1.0562x over previous
#include <cuda_runtime.h>
#include <cstdint>

typedef unsigned long long ull;

#define Bsz 1024
#define Tt 64
#define Dd 128
#define Hh 128
#define ATT 64
#define HOR 24
#define G 8
#define NCTAS (Bsz/G)
#define NTHR 512

// ---------------- device scratch ----------------
__device__ float g_WihT[Dd * 4 * Hh];   // [k][o] 128 x 512
__device__ float g_WhhT[Hh * 4 * Hh];   // [k][o] 128 x 512
__device__ float g_WhhTd[Hh * 4 * Hh];  // [k][o] 128 x 512
__device__ float g_hid[(size_t)Bsz * Tt * Hh];   // encoder hiddens [b][t][h]
__device__ float g_proj[(size_t)Bsz * ATT * Tt]; // enc_proj transposed [b][a][t]

// ---------------- helpers ----------------
__device__ __forceinline__ float tanh_fast(float x) {
    float y; asm("tanh.approx.f32 %0, %1;" : "=f"(y) : "f"(x)); return y;
}
__device__ __forceinline__ float sigm(float x) { return 1.f / (1.f + __expf(-x)); }
__device__ __forceinline__ float tanh_acc(float x) {
    float ax = fabsf(x);
    float e = __expf(-2.f * ax);
    float t = (1.f - e) / (1.f + e);
    return copysignf(t, x);
}
__device__ __forceinline__ ull pack2(float lo, float hi) {
    ull r; asm("mov.b64 %0, {%1,%2};" : "=l"(r) : "f"(lo), "f"(hi)); return r;
}
__device__ __forceinline__ float2 unpack2(ull v) {
    float2 r; asm("mov.b64 {%0,%1}, %2;" : "=f"(r.x), "=f"(r.y) : "l"(v)); return r;
}
__device__ __forceinline__ void ffma2(ull &d, ull a, ull b) {
    asm("fma.rn.f32x2 %0, %1, %2, %0;" : "+l"(d) : "l"(a), "l"(b));
}
__device__ __forceinline__ void barw(int id) {  // warpgroup barrier (128 thr)
    asm volatile("bar.sync %0, 128;" :: "r"(id) : "memory");
}
__device__ __forceinline__ void barg(int id) {  // softmax-group barrier (64 thr)
    asm volatile("bar.sync %0, 64;" :: "r"(id) : "memory");
}

// ---------------- prologue: transpose LSTM weights ----------------
__global__ void transpose_k(const float* __restrict__ Wih,
                            const float* __restrict__ Whh,
                            const float* __restrict__ Wdh) {
    int i = blockIdx.x * blockDim.x + threadIdx.x;
    if (i < 512 * 128) {
        int o = i >> 7, k = i & 127;
        g_WihT[k * 512 + o]  = Wih[i];
        g_WhhT[k * 512 + o]  = Whh[i];
        g_WhhTd[k * 512 + o] = Wdh[i];
    }
}

// smem float offsets (all even; float4 regions 4-aligned)
#define OFF_W      0
#define SZ_W       24704              // 64*386 (enc uses stride 258, dec 386)
#define OFF_H      (OFF_W + SZ_W)     // 1024
#define OFF_C      (OFF_H + 1024)
#define OFF_X      (OFF_C + 1024)     // staging / context
#define OFF_XD     (OFF_X + 1024)     // x_tilde duplicated [g][2k]
#define OFF_HD     (OFF_XD + 2048)    // h duplicated [g][2k]
#define OFF_BASE   (OFF_HD + 2048)
#define OFF_SC     (OFF_BASE + 512)
#define OFF_GATES  (OFF_SC + 512)
#define OFF_BIAS   (OFF_GATES + 4096)
#define OFF_WEB    (OFF_BIAS + 512)
#define OFF_VEW    (OFF_WEB + 64)
#define OFF_WDB    (OFF_VEW + 64)
#define OFF_VDW    (OFF_WDB + 64)
#define OFF_DWIH   (OFF_VDW + 64)
#define OFF_FCW    (OFF_DWIH + 512)
#define OFF_YH     (OFF_FCW + 320)
#define OFF_RED    (OFF_YH + 512)
#define OFF_RED2   (OFF_RED + 16)
#define OFF_YPREV  (OFF_RED2 + 16)
#define SMEM_FLOATS (OFF_YPREV + 8)
#define SMEM_BYTES  (SMEM_FLOATS * 4)

__global__ void __launch_bounds__(NTHR, 1)
darnn_kernel(const float* __restrict__ X,        const float* __restrict__ y_hist,
             const float* __restrict__ We_w,     const float* __restrict__ We_b,
             const float* __restrict__ ve_w,     const float* __restrict__ ve_b,
             const float* __restrict__ enc_bih,  const float* __restrict__ enc_bhh,
             const float* __restrict__ dec_Wih,  const float* __restrict__ dec_bih,
             const float* __restrict__ dec_bhh,
             const float* __restrict__ Wd_w,     const float* __restrict__ Wd_b,
             const float* __restrict__ vd_w,     const float* __restrict__ vd_b,
             const float* __restrict__ fc_w,     const float* __restrict__ fc_b,
             float* __restrict__ out) {
    extern __shared__ float sm[];
    float* sW      = sm + OFF_W;
    float* s_h     = sm + OFF_H;
    float* s_c     = sm + OFF_C;
    float* s_x     = sm + OFF_X;
    float* s_xd    = sm + OFF_XD;
    float* s_hd    = sm + OFF_HD;
    float* s_base  = sm + OFF_BASE;
    float* s_sc    = sm + OFF_SC;
    float* s_gates = sm + OFF_GATES;
    float* s_bias  = sm + OFF_BIAS;
    float* s_Web   = sm + OFF_WEB;
    float* s_vew   = sm + OFF_VEW;
    float* s_Wdb   = sm + OFF_WDB;
    float* s_vdw   = sm + OFF_VDW;
    float* s_dWih  = sm + OFF_DWIH;
    float* s_fcw   = sm + OFF_FCW;
    float* s_yh    = sm + OFF_YH;
    float* s_red   = sm + OFF_RED;
    float* s_red2  = sm + OFF_RED2;
    float* s_yprev = sm + OFF_YPREV;

    const int tid  = threadIdx.x;
    const int lane = tid & 31;
    const int wrp  = tid >> 5;
    const int gg   = tid >> 7;          // warpgroup 0..3
    const int wt   = tid & 127;         // wg-local thread
    const int g0   = gg * 2, g1 = g0 + 1;
    const int gl   = g0 + (wt >> 6);    // this thread's softmax group's g
    const int a63  = wt & 63;
    const int WB   = 1 + gg;            // wg barrier id 1..4
    const int GB   = 5 + gl;            // group barrier id 5..12
    const int b0   = blockIdx.x * G;

    const float ve_b_r = ve_b[0];

    // ---------- preload (encoder) ----------
    for (int i = tid; i < 64 * 257; i += NTHR) {
        int r = i / 257, c = i - r * 257;
        sW[r * 258 + c] = We_w[i];         // stride 258 (8B-aligned rows)
    }
    if (tid < 512) s_bias[tid] = enc_bih[tid] + enc_bhh[tid];
    if (tid < 64) { s_Web[tid] = We_b[tid]; s_vew[tid] = ve_w[tid]; }
    if (tid < G * Tt) s_yh[tid] = y_hist[b0 * Tt + tid];
    for (int i = tid; i < 1024; i += NTHR) { s_h[i] = 0.f; s_c[i] = 0.f; }
    for (int i = tid; i < 2048; i += NTHR) s_hd[i] = 0.f;
    __syncthreads();

    const ulonglong2* WihP  = reinterpret_cast<const ulonglong2*>(g_WihT);
    const ulonglong2* WhhP  = reinterpret_cast<const ulonglong2*>(g_WhhT);
    const ulonglong2* WhhPd = reinterpret_cast<const ulonglong2*>(g_WhhTd);
    const float4* s_bias4 = reinterpret_cast<const float4*>(s_bias);
    float4* s_gates4 = reinterpret_cast<float4*>(s_gates);

    // ================= ENCODER: 64 steps =================
    for (int t = 0; t < Tt; ++t) {
        // E2: base[gl][a] = We_b + [h;c]·Whs_row  (f32x2 over k-pairs)
        {
            const ull* Wr2 = (const ull*)(sW + a63 * 258);
            const ull* hg2 = (const ull*)(s_h + gl * 128);
            const ull* cg2 = (const ull*)(s_c + gl * 128);
            ull acc2 = pack2(s_Web[a63], 0.f);
            #pragma unroll 8
            for (int j = 0; j < 64; ++j) ffma2(acc2, Wr2[j], hg2[j]);
            #pragma unroll 8
            for (int j = 0; j < 64; ++j) ffma2(acc2, Wr2[64 + j], cg2[j]);
            float2 r = unpack2(acc2);
            s_base[gl * 64 + a63] = r.x + r.y;
        }
        barg(GB);
        // E3+E4: attention scores, softmax over D, x_tilde (dup-stored)
        {
            const float* Xg = X + ((size_t)(b0 + gl) * Tt + t) * Dd;
            float x1 = Xg[a63], x2 = Xg[a63 + 64];
            float s1 = ve_b_r, s2 = ve_b_r;
            const float* bg = s_base + gl * 64;
            #pragma unroll 4
            for (int a = 0; a < 64; ++a) {
                float ba = bg[a];
                float wf = sW[a * 258 + 256];
                float vw = s_vew[a];
                s1 = fmaf(vw, tanh_fast(fmaf(x1, wf, ba)), s1);
                s2 = fmaf(vw, tanh_fast(fmaf(x2, wf, ba)), s2);
            }
            float m = fmaxf(s1, s2);
            #pragma unroll
            for (int o = 16; o; o >>= 1) m = fmaxf(m, __shfl_xor_sync(0xffffffffu, m, o));
            if (lane == 0) s_red[wrp] = m;
            barg(GB);
            float gm = fmaxf(s_red[2 * gl], s_red[2 * gl + 1]);
            float e1 = __expf(s1 - gm), e2 = __expf(s2 - gm);
            float ss = e1 + e2;
            #pragma unroll
            for (int o = 16; o; o >>= 1) ss += __shfl_xor_sync(0xffffffffu, ss, o);
            if (lane == 0) s_red2[wrp] = ss;
            barg(GB);
            float inv = 1.f / (s_red2[2 * gl] + s_red2[2 * gl + 1]);
            float v1 = x1 * e1 * inv, v2 = x2 * e2 * inv;
            *(float2*)(s_xd + gl * 256 + 2 * a63)       = make_float2(v1, v1);
            *(float2*)(s_xd + gl * 256 + 128 + 2 * a63) = make_float2(v2, v2);
        }
        barw(WB);
        // E5: gates via packed FFMA2 (o-pairs)
        {
            const int og = wt;
            float4 b4 = s_bias4[og];
            ull acc00 = pack2(b4.x, b4.y), acc01 = pack2(b4.z, b4.w);
            ull acc10 = acc00, acc11 = acc01;
            const ull* xd0 = (const ull*)(s_xd + g0 * 256);
            const ull* xd1 = (const ull*)(s_xd + g1 * 256);
            #pragma unroll 4
            for (int k = 0; k < 128; ++k) {
                ulonglong2 w = WihP[k * 128 + og];
                ull xa = xd0[k], xb = xd1[k];
                ffma2(acc00, w.x, xa); ffma2(acc01, w.y, xa);
                ffma2(acc10, w.x, xb); ffma2(acc11, w.y, xb);
            }
            const ull* hd0 = (const ull*)(s_hd + g0 * 256);
            const ull* hd1 = (const ull*)(s_hd + g1 * 256);
            #pragma unroll 4
            for (int k = 0; k < 128; ++k) {
                ulonglong2 w = WhhP[k * 128 + og];
                ull ha = hd0[k], hb = hd1[k];
                ffma2(acc00, w.x, ha); ffma2(acc01, w.y, ha);
                ffma2(acc10, w.x, hb); ffma2(acc11, w.y, hb);
            }
            float2 p = unpack2(acc00), q = unpack2(acc01);
            s_gates4[g0 * 128 + og] = make_float4(p.x, p.y, q.x, q.y);
            p = unpack2(acc10); q = unpack2(acc11);
            s_gates4[g1 * 128 + og] = make_float4(p.x, p.y, q.x, q.y);
        }
        barw(WB);
        // E6: LSTM cell update for g0,g1
        {
            const int u = wt;
            #pragma unroll
            for (int q = 0; q < 2; ++q) {
                int g = g0 + q;
                const float* gr = s_gates + g * 512;
                float ig = sigm(gr[u]);
                float fg = sigm(gr[128 + u]);
                float gv = tanh_acc(gr[256 + u]);
                float ov = sigm(gr[384 + u]);
                float c2 = fmaf(fg, s_c[g * 128 + u], ig * gv);
                float h2 = ov * tanh_acc(c2);
                s_c[g * 128 + u] = c2;
                s_h[g * 128 + u] = h2;
                *(float2*)(s_hd + g * 256 + 2 * u) = make_float2(h2, h2);
                g_hid[((size_t)(b0 + g) * Tt + t) * Hh + u] = h2;
            }
        }
        __syncthreads();   // step end: bounds wg drift (L1 weight-line sharing)
    }

    // ================= enc_proj =================
    for (int i = tid; i < 64 * 384; i += NTHR) {
        int r = i / 384, c = i - r * 384;
        sW[r * 386 + c] = Wd_w[i];         // stride 386 (8B-aligned rows)
    }
    __syncthreads();
    for (int t = 0; t < Tt; ++t) {
        s_x[g0 * 128 + wt] = g_hid[((size_t)(b0 + g0) * Tt + t) * Hh + wt];
        s_x[g1 * 128 + wt] = g_hid[((size_t)(b0 + g1) * Tt + t) * Hh + wt];
        barw(WB);
        {
            const ull* Wr2 = (const ull*)(sW + a63 * 386);
            const ull* hg2 = (const ull*)(s_x + gl * 128);
            ull acc2 = 0ULL;
            #pragma unroll 8
            for (int j = 0; j < 64; ++j) ffma2(acc2, Wr2[j], hg2[j]);
            float2 r = unpack2(acc2);
            g_proj[((size_t)(b0 + gl)) * ATT * Tt + a63 * Tt + t] = r.x + r.y;
        }
        barw(WB);
    }

    // ---------- preload (decoder) ----------
    __syncthreads();
    if (tid < 512) {
        s_bias[tid] = dec_bih[tid] + dec_bhh[tid];
        s_dWih[tid] = dec_Wih[tid];
    }
    if (tid < 64) { s_Wdb[tid] = Wd_b[tid]; s_vdw[tid] = vd_w[tid]; }
    if (tid < 320) s_fcw[tid] = fc_w[tid];
    for (int i = tid; i < 1024; i += NTHR) { s_h[i] = 0.f; s_c[i] = 0.f; }
    for (int i = tid; i < 2048; i += NTHR) s_hd[i] = 0.f;
    if (tid < G) s_yprev[tid] = s_yh[tid * Tt + Tt - 1];
    const float vd_b_r = vd_b[0];
    const float fc_b_r = fc_b[0];
    const float4* s_dWih4 = reinterpret_cast<const float4*>(s_dWih);
    __syncthreads();

    // ================= DECODER: 24 steps =================
    for (int s = 0; s < HOR; ++s) {
        // D1: dc[gl][a]  (f32x2 over k-pairs)
        {
            const ull* Wd2 = (const ull*)(sW + a63 * 386 + 128);
            const ull* Wc2 = (const ull*)(sW + a63 * 386 + 256);
            const ull* dg2 = (const ull*)(s_h + gl * 128);
            const ull* cg2 = (const ull*)(s_c + gl * 128);
            ull acc2 = pack2(s_Wdb[a63], 0.f);
            #pragma unroll 8
            for (int j = 0; j < 64; ++j) ffma2(acc2, Wd2[j], dg2[j]);
            #pragma unroll 8
            for (int j = 0; j < 64; ++j) ffma2(acc2, Wc2[j], cg2[j]);
            float2 r = unpack2(acc2);
            s_base[gl * 64 + a63] = r.x + r.y;
        }
        barg(GB);
        // D2+D3: temporal scores + softmax -> beta
        {
            const float* pp = g_proj + ((size_t)(b0 + gl)) * ATT * Tt + a63;
            const float* bg = s_base + gl * 64;
            float acc = vd_b_r;
            #pragma unroll 4
            for (int a = 0; a < 64; ++a)
                acc = fmaf(s_vdw[a], tanh_fast(pp[a * 64] + bg[a]), acc);
            float m = acc;
            #pragma unroll
            for (int o = 16; o; o >>= 1) m = fmaxf(m, __shfl_xor_sync(0xffffffffu, m, o));
            if (lane == 0) s_red[wrp] = m;
            barg(GB);
            float gm = fmaxf(s_red[2 * gl], s_red[2 * gl + 1]);
            float e = __expf(acc - gm);
            float ssum = e;
            #pragma unroll
            for (int o = 16; o; o >>= 1) ssum += __shfl_xor_sync(0xffffffffu, ssum, o);
            if (lane == 0) s_red2[wrp] = ssum;
            barg(GB);
            float inv = 1.f / (s_red2[2 * gl] + s_red2[2 * gl + 1]);
            s_sc[gl * 64 + a63] = e * inv;
        }
        barw(WB);
        // D4: context[g][u] -> s_x
        {
            const int u = wt;
            #pragma unroll
            for (int q = 0; q < 2; ++q) {
                int g = g0 + q;
                const float* hp = g_hid + ((size_t)(b0 + g)) * Tt * Hh + u;
                const float* be = s_sc + g * 64;
                float acc = 0.f;
                #pragma unroll 8
                for (int tt = 0; tt < 64; ++tt) acc = fmaf(be[tt], hp[tt * 128], acc);
                s_x[g * 128 + u] = acc;
            }
        }
        // D5: decoder LSTM gates (scalar y input, f32x2 Whh)
        {
            const int og = wt;
            float4 b4 = s_bias4[og];
            float4 w4 = s_dWih4[og];
            float y0 = s_yprev[g0], y1 = s_yprev[g1];
            ull acc00 = pack2(fmaf(w4.x, y0, b4.x), fmaf(w4.y, y0, b4.y));
            ull acc01 = pack2(fmaf(w4.z, y0, b4.z), fmaf(w4.w, y0, b4.w));
            ull acc10 = pack2(fmaf(w4.x, y1, b4.x), fmaf(w4.y, y1, b4.y));
            ull acc11 = pack2(fmaf(w4.z, y1, b4.z), fmaf(w4.w, y1, b4.w));
            const ull* hd0 = (const ull*)(s_hd + g0 * 256);
            const ull* hd1 = (const ull*)(s_hd + g1 * 256);
            #pragma unroll 4
            for (int k = 0; k < 128; ++k) {
                ulonglong2 w = WhhPd[k * 128 + og];
                ull ha = hd0[k], hb = hd1[k];
                ffma2(acc00, w.x, ha); ffma2(acc01, w.y, ha);
                ffma2(acc10, w.x, hb); ffma2(acc11, w.y, hb);
            }
            float2 p = unpack2(acc00), q = unpack2(acc01);
            s_gates4[g0 * 128 + og] = make_float4(p.x, p.y, q.x, q.y);
            p = unpack2(acc10); q = unpack2(acc11);
            s_gates4[g1 * 128 + og] = make_float4(p.x, p.y, q.x, q.y);
        }
        barw(WB);
        // D6: LSTM update
        {
            const int u = wt;
            #pragma unroll
            for (int q = 0; q < 2; ++q) {
                int g = g0 + q;
                const float* gr = s_gates + g * 512;
                float ig = sigm(gr[u]);
                float fg = sigm(gr[128 + u]);
                float gv = tanh_acc(gr[256 + u]);
                float ov = sigm(gr[384 + u]);
                float c2 = fmaf(fg, s_c[g * 128 + u], ig * gv);
                float h2 = ov * tanh_acc(c2);
                s_c[g * 128 + u] = c2;
                s_h[g * 128 + u] = h2;
                *(float2*)(s_hd + g * 256 + 2 * u) = make_float2(h2, h2);
            }
        }
        barw(WB);
        // D7: fc  out = fc_b + fc_w · [d2, context, y_hist]
        {
            int w4i = wt >> 5;     // warp-in-wg 0..3
            if (w4i < 2) {
                int g = g0 + w4i;
                float acc = 0.f;
                for (int idx = lane; idx < 320; idx += 32) {
                    float v;
                    if (idx < 128)       v = s_h[g * 128 + idx];
                    else if (idx < 256)  v = s_x[g * 128 + idx - 128];
                    else                 v = s_yh[g * 64 + idx - 256];
                    acc = fmaf(s_fcw[idx], v, acc);
                }
                #pragma unroll
                for (int o = 16; o; o >>= 1) acc += __shfl_xor_sync(0xffffffffu, acc, o);
                if (lane == 0) {
                    float ov = acc + fc_b_r;
                    s_yprev[g] = ov;
                    out[(b0 + g) * HOR + s] = ov;
                }
            }
        }
        __syncthreads();   // step end
    }
}

extern "C" void kernel_launch(void* const* d_in, const int* in_sizes, int n_in,
                              void* d_out, int out_size) {
    const float* X        = (const float*)d_in[0];
    const float* y_hist   = (const float*)d_in[1];
    const float* We_w     = (const float*)d_in[2];
    const float* We_b     = (const float*)d_in[3];
    const float* ve_w     = (const float*)d_in[4];
    const float* ve_b     = (const float*)d_in[5];
    const float* enc_Wih  = (const float*)d_in[6];
    const float* enc_Whh  = (const float*)d_in[7];
    const float* enc_bih  = (const float*)d_in[8];
    const float* enc_bhh  = (const float*)d_in[9];
    const float* dec_Wih  = (const float*)d_in[10];
    const float* dec_Whh  = (const float*)d_in[11];
    const float* dec_bih  = (const float*)d_in[12];
    const float* dec_bhh  = (const float*)d_in[13];
    const float* Wd_w     = (const float*)d_in[14];
    const float* Wd_b     = (const float*)d_in[15];
    const float* vd_w     = (const float*)d_in[16];
    const float* vd_b     = (const float*)d_in[17];
    const float* fc_w     = (const float*)d_in[18];
    const float* fc_b     = (const float*)d_in[19];
    float* out = (float*)d_out;

    cudaFuncSetAttribute(darnn_kernel,
                         cudaFuncAttributeMaxDynamicSharedMemorySize, SMEM_BYTES);

    transpose_k<<<(512 * 128 + 255) / 256, 256>>>(enc_Wih, enc_Whh, dec_Whh);
    darnn_kernel<<<NCTAS, NTHR, SMEM_BYTES>>>(
        X, y_hist, We_w, We_b, ve_w, ve_b,
        enc_bih, enc_bhh, dec_Wih, dec_bih, dec_bhh,
        Wd_w, Wd_b, vd_w, vd_b, fc_w, fc_b, out);
}

// round 5
// speedup vs baseline: 1.3434x; 1.2720x over previous
#include <cuda_runtime.h>
#include <cstdint>

typedef unsigned long long ull;

#define Bsz 1024
#define Tt 64
#define Dd 128
#define Hh 128
#define ATT 64
#define HOR 24
#define G 8
#define NCTAS (Bsz/G)
#define NTHR 512

// ---------------- device scratch ----------------
__device__ float g_WihT[Dd * 4 * Hh];   // [k][o] 128 x 512
__device__ float g_WhhT[Hh * 4 * Hh];   // [k][o] 128 x 512
__device__ float g_WhhTd[Hh * 4 * Hh];  // [k][o] 128 x 512
__device__ float g_hid[(size_t)Bsz * Tt * Hh];   // encoder hiddens [b][t][h]
__device__ float g_proj[(size_t)Bsz * ATT * Tt]; // enc_proj transposed [b][a][t]

// ---------------- helpers ----------------
__device__ __forceinline__ float tanh_fast(float x) {
    float y; asm("tanh.approx.f32 %0, %1;" : "=f"(y) : "f"(x)); return y;
}
__device__ __forceinline__ float sigm(float x) { return 1.f / (1.f + __expf(-x)); }
__device__ __forceinline__ float tanh_acc(float x) {
    float ax = fabsf(x);
    float e = __expf(-2.f * ax);
    float t = (1.f - e) / (1.f + e);
    return copysignf(t, x);
}
__device__ __forceinline__ ull pack2(float lo, float hi) {
    ull r; asm("mov.b64 %0, {%1,%2};" : "=l"(r) : "f"(lo), "f"(hi)); return r;
}
__device__ __forceinline__ float2 unpack2(ull v) {
    float2 r; asm("mov.b64 {%0,%1}, %2;" : "=f"(r.x), "=f"(r.y) : "l"(v)); return r;
}
__device__ __forceinline__ void ffma2(ull &d, ull a, ull b) {
    asm("fma.rn.f32x2 %0, %1, %2, %0;" : "+l"(d) : "l"(a), "l"(b));
}
__device__ __forceinline__ void barg(int id) {  // softmax-group barrier (64 thr)
    asm volatile("bar.sync %0, 64;" :: "r"(id) : "memory");
}
__device__ __forceinline__ void barw(int id) {  // warpgroup barrier (128 thr)
    asm volatile("bar.sync %0, 128;" :: "r"(id) : "memory");
}

// ---------------- prologue: transpose LSTM weights ----------------
__global__ void transpose_k(const float* __restrict__ Wih,
                            const float* __restrict__ Whh,
                            const float* __restrict__ Wdh) {
    int i = blockIdx.x * blockDim.x + threadIdx.x;
    if (i < 512 * 128) {
        int o = i >> 7, k = i & 127;
        g_WihT[k * 512 + o]  = Wih[i];
        g_WhhT[k * 512 + o]  = Whh[i];
        g_WhhTd[k * 512 + o] = Wdh[i];
    }
}

// smem float offsets (all even; float4 regions 4-aligned)
#define OFF_W      0
#define SZ_W       24704              // 64*386 (enc uses stride 258, dec 386)
#define OFF_H      (OFF_W + SZ_W)
#define OFF_C      (OFF_H + 1024)
#define OFF_X      (OFF_C + 1024)     // staging / context
#define OFF_XD     (OFF_X + 1024)     // x_tilde duplicated [g][2k]
#define OFF_HD     (OFF_XD + 2048)    // h duplicated [g][2k]
#define OFF_BASE   (OFF_HD + 2048)
#define OFF_SC     (OFF_BASE + 512)
#define OFF_GA     (OFF_SC + 512)     // gate partials (k-half 0) [g][512]
#define OFF_GB     (OFF_GA + 4096)    // gate partials (k-half 1) [g][512]
#define OFF_BIAS   (OFF_GB + 4096)
#define OFF_WEB    (OFF_BIAS + 512)
#define OFF_VEW    (OFF_WEB + 64)
#define OFF_WDB    (OFF_VEW + 64)
#define OFF_VDW    (OFF_WDB + 64)
#define OFF_DWIH   (OFF_VDW + 64)
#define OFF_FCW    (OFF_DWIH + 512)
#define OFF_YH     (OFF_FCW + 320)
#define OFF_RED    (OFF_YH + 512)
#define OFF_RED2   (OFF_RED + 16)
#define OFF_YPREV  (OFF_RED2 + 16)
#define SMEM_FLOATS (OFF_YPREV + 8)
#define SMEM_BYTES  (SMEM_FLOATS * 4)

__global__ void __launch_bounds__(NTHR, 1)
darnn_kernel(const float* __restrict__ X,        const float* __restrict__ y_hist,
             const float* __restrict__ We_w,     const float* __restrict__ We_b,
             const float* __restrict__ ve_w,     const float* __restrict__ ve_b,
             const float* __restrict__ enc_bih,  const float* __restrict__ enc_bhh,
             const float* __restrict__ dec_Wih,  const float* __restrict__ dec_bih,
             const float* __restrict__ dec_bhh,
             const float* __restrict__ Wd_w,     const float* __restrict__ Wd_b,
             const float* __restrict__ vd_w,     const float* __restrict__ vd_b,
             const float* __restrict__ fc_w,     const float* __restrict__ fc_b,
             float* __restrict__ out) {
    extern __shared__ float sm[];
    float* sW      = sm + OFF_W;
    float* s_h     = sm + OFF_H;
    float* s_c     = sm + OFF_C;
    float* s_x     = sm + OFF_X;
    float* s_xd    = sm + OFF_XD;
    float* s_hd    = sm + OFF_HD;
    float* s_base  = sm + OFF_BASE;
    float* s_sc    = sm + OFF_SC;
    float* s_gA    = sm + OFF_GA;
    float* s_gB    = sm + OFF_GB;
    float* s_bias  = sm + OFF_BIAS;
    float* s_Web   = sm + OFF_WEB;
    float* s_vew   = sm + OFF_VEW;
    float* s_Wdb   = sm + OFF_WDB;
    float* s_vdw   = sm + OFF_VDW;
    float* s_dWih  = sm + OFF_DWIH;
    float* s_fcw   = sm + OFF_FCW;
    float* s_yh    = sm + OFF_YH;
    float* s_red   = sm + OFF_RED;
    float* s_red2  = sm + OFF_RED2;
    float* s_yprev = sm + OFF_YPREV;

    const int tid  = threadIdx.x;
    const int lane = tid & 31;
    const int wrp  = tid >> 5;
    const int grp  = tid >> 6;          // softmax group 0..7 (one batch row)
    const int a63  = tid & 63;
    const int GBid = 5 + grp;           // named barrier 5..12 (64 threads)
    const int op   = tid & 255;         // o-pair 0..255 (gate GEMM)
    const int kh   = tid >> 8;          // k-half 0/1 (gate GEMM)
    const int u128 = tid & 127;
    const int gb   = tid >> 7;
    const int wt   = tid & 127;
    const int gg   = tid >> 7;
    const int g0p  = gg * 2, g1p = g0p + 1;   // for enc_proj phase
    const int glp  = g0p + (wt >> 6);
    const int WB   = 1 + gg;
    const int b0   = blockIdx.x * G;

    const float ve_b_r = ve_b[0];

    // ---------- preload (encoder) ----------
    for (int i = tid; i < 64 * 257; i += NTHR) {
        int r = i / 257, c = i - r * 257;
        sW[r * 258 + c] = We_w[i];
    }
    if (tid < 512) s_bias[tid] = enc_bih[tid] + enc_bhh[tid];
    if (tid < 64) { s_Web[tid] = We_b[tid]; s_vew[tid] = ve_w[tid]; }
    if (tid < G * Tt) s_yh[tid] = y_hist[b0 * Tt + tid];
    for (int i = tid; i < 1024; i += NTHR) { s_h[i] = 0.f; s_c[i] = 0.f; }
    for (int i = tid; i < 2048; i += NTHR) s_hd[i] = 0.f;
    __syncthreads();

    const ull* WihP  = reinterpret_cast<const ull*>(g_WihT);   // [k][256] pairs
    const ull* WhhP  = reinterpret_cast<const ull*>(g_WhhT);
    const ull* WhhPd = reinterpret_cast<const ull*>(g_WhhTd);

    // gate-GEMM sources for this thread (encoder)
    const ull*   myW   = kh ? WhhP : WihP;
    const float* myDup = kh ? s_hd : s_xd;
    float*       myDst = kh ? s_gB : s_gA;

    // ================= ENCODER: 64 steps =================
    for (int t = 0; t < Tt; ++t) {
        // E2: base[grp][a] = We_b + [h;c]·Whs_row  (2 interleaved f32x2 chains)
        {
            const ull* Wr2 = (const ull*)(sW + a63 * 258);
            const ull* hg2 = (const ull*)(s_h + grp * 128);
            const ull* cg2 = (const ull*)(s_c + grp * 128);
            ull aA = pack2(s_Web[a63], 0.f), aB = 0ULL;
            #pragma unroll 8
            for (int j = 0; j < 64; j += 2) {
                ffma2(aA, Wr2[j],     hg2[j]);
                ffma2(aB, Wr2[j + 1], hg2[j + 1]);
            }
            #pragma unroll 8
            for (int j = 0; j < 64; j += 2) {
                ffma2(aA, Wr2[64 + j],     cg2[j]);
                ffma2(aB, Wr2[64 + j + 1], cg2[j + 1]);
            }
            float2 ra = unpack2(aA), rb = unpack2(aB);
            s_base[grp * 64 + a63] = (ra.x + rb.x) + (ra.y + rb.y);
        }
        barg(GBid);
        // E3+E4: attention scores, softmax over D, x_tilde (dup-stored)
        {
            const float* Xg = X + ((size_t)(b0 + grp) * Tt + t) * Dd;
            float x1 = Xg[a63], x2 = Xg[a63 + 64];
            float s1a = ve_b_r, s1b = 0.f, s2a = 0.f, s2b = 0.f;
            const float* bg = s_base + grp * 64;
            #pragma unroll 4
            for (int a = 0; a < 64; a += 2) {
                float ba0 = bg[a],     wf0 = sW[a * 258 + 256],       vw0 = s_vew[a];
                float ba1 = bg[a + 1], wf1 = sW[(a + 1) * 258 + 256], vw1 = s_vew[a + 1];
                s1a = fmaf(vw0, tanh_fast(fmaf(x1, wf0, ba0)), s1a);
                s1b = fmaf(vw1, tanh_fast(fmaf(x1, wf1, ba1)), s1b);
                s2a = fmaf(vw0, tanh_fast(fmaf(x2, wf0, ba0)), s2a);
                s2b = fmaf(vw1, tanh_fast(fmaf(x2, wf1, ba1)), s2b);
            }
            float s1 = s1a + s1b, s2 = (s2a + s2b) + ve_b_r;
            float m = fmaxf(s1, s2);
            #pragma unroll
            for (int o = 16; o; o >>= 1) m = fmaxf(m, __shfl_xor_sync(0xffffffffu, m, o));
            if (lane == 0) s_red[wrp] = m;
            barg(GBid);
            float gm = fmaxf(s_red[2 * grp], s_red[2 * grp + 1]);
            float e1 = __expf(s1 - gm), e2 = __expf(s2 - gm);
            float ss = e1 + e2;
            #pragma unroll
            for (int o = 16; o; o >>= 1) ss += __shfl_xor_sync(0xffffffffu, ss, o);
            if (lane == 0) s_red2[wrp] = ss;
            barg(GBid);
            float inv = 1.f / (s_red2[2 * grp] + s_red2[2 * grp + 1]);
            float v1 = x1 * e1 * inv, v2 = x2 * e2 * inv;
            *(float2*)(s_xd + grp * 256 + 2 * a63)       = make_float2(v1, v1);
            *(float2*)(s_xd + grp * 256 + 128 + 2 * a63) = make_float2(v2, v2);
        }
        __syncthreads();
        // E5: gate partials. Thread = (op, kh); 8 batch-row accumulators.
        {
            ull acc[8];
            #pragma unroll
            for (int g = 0; g < 8; ++g) acc[g] = 0ULL;
            #pragma unroll 2
            for (int k = 0; k < 128; k += 2) {
                ull w0 = myW[k * 256 + op];
                ull w1 = myW[(k + 1) * 256 + op];
                #pragma unroll
                for (int g = 0; g < 8; ++g) {
                    ulonglong2 xp = *(const ulonglong2*)(myDup + g * 256 + 2 * k);
                    ffma2(acc[g], w0, xp.x);
                    ffma2(acc[g], w1, xp.y);
                }
            }
            #pragma unroll
            for (int g = 0; g < 8; ++g) {
                float2 r = unpack2(acc[g]);
                *(float2*)(myDst + g * 512 + 2 * op) = r;
            }
        }
        __syncthreads();
        // E6: LSTM cell update (sum partials + bias)
        {
            #pragma unroll
            for (int q = 0; q < 2; ++q) {
                int g = gb + q * 4;
                const float* ga = s_gA + g * 512;
                const float* gbp = s_gB + g * 512;
                float gi = sigm(ga[u128]       + gbp[u128]       + s_bias[u128]);
                float gf = sigm(ga[128 + u128] + gbp[128 + u128] + s_bias[128 + u128]);
                float gv = tanh_acc(ga[256 + u128] + gbp[256 + u128] + s_bias[256 + u128]);
                float go = sigm(ga[384 + u128] + gbp[384 + u128] + s_bias[384 + u128]);
                float c2 = fmaf(gf, s_c[g * 128 + u128], gi * gv);
                float h2 = go * tanh_acc(c2);
                s_c[g * 128 + u128] = c2;
                s_h[g * 128 + u128] = h2;
                *(float2*)(s_hd + g * 256 + 2 * u128) = make_float2(h2, h2);
                g_hid[((size_t)(b0 + g) * Tt + t) * Hh + u128] = h2;
            }
        }
        __syncthreads();
    }

    // ================= enc_proj =================
    for (int i = tid; i < 64 * 384; i += NTHR) {
        int r = i / 384, c = i - r * 384;
        sW[r * 386 + c] = Wd_w[i];
    }
    __syncthreads();
    for (int t = 0; t < Tt; ++t) {
        s_x[g0p * 128 + wt] = g_hid[((size_t)(b0 + g0p) * Tt + t) * Hh + wt];
        s_x[g1p * 128 + wt] = g_hid[((size_t)(b0 + g1p) * Tt + t) * Hh + wt];
        barw(WB);
        {
            const ull* Wr2 = (const ull*)(sW + a63 * 386);
            const ull* hg2 = (const ull*)(s_x + glp * 128);
            ull aA = 0ULL, aB = 0ULL;
            #pragma unroll 8
            for (int j = 0; j < 64; j += 2) {
                ffma2(aA, Wr2[j], hg2[j]);
                ffma2(aB, Wr2[j + 1], hg2[j + 1]);
            }
            float2 ra = unpack2(aA), rb = unpack2(aB);
            g_proj[((size_t)(b0 + glp)) * ATT * Tt + a63 * Tt + t] = (ra.x + rb.x) + (ra.y + rb.y);
        }
        barw(WB);
    }

    // ---------- preload (decoder) ----------
    __syncthreads();
    if (tid < 512) {
        s_bias[tid] = dec_bih[tid] + dec_bhh[tid];
        s_dWih[tid] = dec_Wih[tid];
    }
    if (tid < 64) { s_Wdb[tid] = Wd_b[tid]; s_vdw[tid] = vd_w[tid]; }
    if (tid < 320) s_fcw[tid] = fc_w[tid];
    for (int i = tid; i < 1024; i += NTHR) { s_h[i] = 0.f; s_c[i] = 0.f; }
    for (int i = tid; i < 2048; i += NTHR) s_hd[i] = 0.f;
    if (tid < G) s_yprev[tid] = s_yh[tid * Tt + Tt - 1];
    const float vd_b_r = vd_b[0];
    const float fc_b_r = fc_b[0];
    __syncthreads();

    // ================= DECODER: 24 steps =================
    for (int s = 0; s < HOR; ++s) {
        // D1: dc[grp][a]  (2 interleaved chains)
        {
            const ull* Wd2 = (const ull*)(sW + a63 * 386 + 128);
            const ull* Wc2 = (const ull*)(sW + a63 * 386 + 256);
            const ull* dg2 = (const ull*)(s_h + grp * 128);
            const ull* cg2 = (const ull*)(s_c + grp * 128);
            ull aA = pack2(s_Wdb[a63], 0.f), aB = 0ULL;
            #pragma unroll 8
            for (int j = 0; j < 64; j += 2) {
                ffma2(aA, Wd2[j], dg2[j]);
                ffma2(aB, Wd2[j + 1], dg2[j + 1]);
            }
            #pragma unroll 8
            for (int j = 0; j < 64; j += 2) {
                ffma2(aA, Wc2[j], cg2[j]);
                ffma2(aB, Wc2[j + 1], cg2[j + 1]);
            }
            float2 ra = unpack2(aA), rb = unpack2(aB);
            s_base[grp * 64 + a63] = (ra.x + rb.x) + (ra.y + rb.y);
        }
        barg(GBid);
        // D2+D3: temporal scores + softmax -> beta
        {
            const float* pp = g_proj + ((size_t)(b0 + grp)) * ATT * Tt + a63;
            const float* bg = s_base + grp * 64;
            float acA = vd_b_r, acB = 0.f;
            #pragma unroll 4
            for (int a = 0; a < 64; a += 2) {
                acA = fmaf(s_vdw[a],     tanh_fast(pp[a * 64] + bg[a]), acA);
                acB = fmaf(s_vdw[a + 1], tanh_fast(pp[(a + 1) * 64] + bg[a + 1]), acB);
            }
            float acc = acA + acB;
            float m = acc;
            #pragma unroll
            for (int o = 16; o; o >>= 1) m = fmaxf(m, __shfl_xor_sync(0xffffffffu, m, o));
            if (lane == 0) s_red[wrp] = m;
            barg(GBid);
            float gm = fmaxf(s_red[2 * grp], s_red[2 * grp + 1]);
            float e = __expf(acc - gm);
            float ssum = e;
            #pragma unroll
            for (int o = 16; o; o >>= 1) ssum += __shfl_xor_sync(0xffffffffu, ssum, o);
            if (lane == 0) s_red2[wrp] = ssum;
            barg(GBid);
            float inv = 1.f / (s_red2[2 * grp] + s_red2[2 * grp + 1]);
            s_sc[grp * 64 + a63] = e * inv;
        }
        __syncthreads();
        // D4: context[g][u] -> s_x
        {
            #pragma unroll
            for (int q = 0; q < 2; ++q) {
                int g = gb + q * 4;
                const float* hp = g_hid + ((size_t)(b0 + g)) * Tt * Hh + u128;
                const float* be = s_sc + g * 64;
                float acA = 0.f, acB = 0.f;
                #pragma unroll 8
                for (int tt = 0; tt < 64; tt += 2) {
                    acA = fmaf(be[tt],     hp[tt * 128], acA);
                    acB = fmaf(be[tt + 1], hp[(tt + 1) * 128], acB);
                }
                s_x[g * 128 + u128] = acA + acB;
            }
        }
        // D5: decoder gate partials via (op, kh) split of Whh's k=128
        {
            ull acc[8];
            #pragma unroll
            for (int g = 0; g < 8; ++g) acc[g] = 0ULL;
            const int kbase = kh * 64;
            #pragma unroll 2
            for (int k = 0; k < 64; k += 2) {
                ull w0 = WhhPd[(kbase + k) * 256 + op];
                ull w1 = WhhPd[(kbase + k + 1) * 256 + op];
                #pragma unroll
                for (int g = 0; g < 8; ++g) {
                    ulonglong2 xp = *(const ulonglong2*)(s_hd + g * 256 + 2 * (kbase + k));
                    ffma2(acc[g], w0, xp.x);
                    ffma2(acc[g], w1, xp.y);
                }
            }
            #pragma unroll
            for (int g = 0; g < 8; ++g) {
                float2 r = unpack2(acc[g]);
                *(float2*)(myDst + g * 512 + 2 * op) = r;
            }
        }
        __syncthreads();
        // D6: LSTM update (sum partials + bias + dWih*y_prev)
        {
            #pragma unroll
            for (int q = 0; q < 2; ++q) {
                int g = gb + q * 4;
                float y = s_yprev[g];
                const float* ga = s_gA + g * 512;
                const float* gbp = s_gB + g * 512;
                float gi = sigm(fmaf(s_dWih[u128], y, ga[u128] + gbp[u128] + s_bias[u128]));
                float gf = sigm(fmaf(s_dWih[128 + u128], y, ga[128 + u128] + gbp[128 + u128] + s_bias[128 + u128]));
                float gv = tanh_acc(fmaf(s_dWih[256 + u128], y, ga[256 + u128] + gbp[256 + u128] + s_bias[256 + u128]));
                float go = sigm(fmaf(s_dWih[384 + u128], y, ga[384 + u128] + gbp[384 + u128] + s_bias[384 + u128]));
                float c2 = fmaf(gf, s_c[g * 128 + u128], gi * gv);
                float h2 = go * tanh_acc(c2);
                s_c[g * 128 + u128] = c2;
                s_h[g * 128 + u128] = h2;
                *(float2*)(s_hd + g * 256 + 2 * u128) = make_float2(h2, h2);
            }
        }
        __syncthreads();
        // D7: fc  out = fc_b + fc_w · [d2, context, y_hist]
        if (wrp < G) {
            int g = wrp;
            float acc = 0.f;
            for (int idx = lane; idx < 320; idx += 32) {
                float v;
                if (idx < 128)       v = s_h[g * 128 + idx];
                else if (idx < 256)  v = s_x[g * 128 + idx - 128];
                else                 v = s_yh[g * 64 + idx - 256];
                acc = fmaf(s_fcw[idx], v, acc);
            }
            #pragma unroll
            for (int o = 16; o; o >>= 1) acc += __shfl_xor_sync(0xffffffffu, acc, o);
            if (lane == 0) {
                float ov = acc + fc_b_r;
                s_yprev[g] = ov;
                out[(b0 + g) * HOR + s] = ov;
            }
        }
        __syncthreads();
    }
}

extern "C" void kernel_launch(void* const* d_in, const int* in_sizes, int n_in,
                              void* d_out, int out_size) {
    const float* X        = (const float*)d_in[0];
    const float* y_hist   = (const float*)d_in[1];
    const float* We_w     = (const float*)d_in[2];
    const float* We_b     = (const float*)d_in[3];
    const float* ve_w     = (const float*)d_in[4];
    const float* ve_b     = (const float*)d_in[5];
    const float* enc_Wih  = (const float*)d_in[6];
    const float* enc_Whh  = (const float*)d_in[7];
    const float* enc_bih  = (const float*)d_in[8];
    const float* enc_bhh  = (const float*)d_in[9];
    const float* dec_Wih  = (const float*)d_in[10];
    const float* dec_Whh  = (const float*)d_in[11];
    const float* dec_bih  = (const float*)d_in[12];
    const float* dec_bhh  = (const float*)d_in[13];
    const float* Wd_w     = (const float*)d_in[14];
    const float* Wd_b     = (const float*)d_in[15];
    const float* vd_w     = (const float*)d_in[16];
    const float* vd_b     = (const float*)d_in[17];
    const float* fc_w     = (const float*)d_in[18];
    const float* fc_b     = (const float*)d_in[19];
    float* out = (float*)d_out;

    cudaFuncSetAttribute(darnn_kernel,
                         cudaFuncAttributeMaxDynamicSharedMemorySize, SMEM_BYTES);

    transpose_k<<<(512 * 128 + 255) / 256, 256>>>(enc_Wih, enc_Whh, dec_Whh);
    darnn_kernel<<<NCTAS, NTHR, SMEM_BYTES>>>(
        X, y_hist, We_w, We_b, ve_w, ve_b,
        enc_bih, enc_bhh, dec_Wih, dec_bih, dec_bhh,
        Wd_w, Wd_b, vd_w, vd_b, fc_w, fc_b, out);
}

// round 6
// speedup vs baseline: 1.4283x; 1.0632x over previous
#include <cuda_runtime.h>
#include <cstdint>

typedef unsigned long long ull;

#define Bsz 1024
#define Tt 64
#define Dd 128
#define Hh 128
#define ATT 64
#define HOR 24
#define G 8
#define NCTAS (Bsz/G)
#define NTHR 512

// ---------------- device scratch ----------------
__device__ float g_WihT[Dd * 4 * Hh];   // [k][o] 128 x 512
__device__ float g_WhhT[Hh * 4 * Hh];   // [k][o] 128 x 512
__device__ float g_WhhTd[Hh * 4 * Hh];  // [k][o] 128 x 512
__device__ float g_hid[(size_t)Bsz * Tt * Hh];   // encoder hiddens [b][t][h]
__device__ float g_proj[(size_t)Bsz * ATT * Tt]; // enc_proj transposed [b][a][t]

// ---------------- helpers ----------------
__device__ __forceinline__ float tanh_fast(float x) {
    float y; asm("tanh.approx.f32 %0, %1;" : "=f"(y) : "f"(x)); return y;
}
__device__ __forceinline__ float sigm(float x) { return 1.f / (1.f + __expf(-x)); }
__device__ __forceinline__ float tanh_acc(float x) {
    float ax = fabsf(x);
    float e = __expf(-2.f * ax);
    float t = (1.f - e) / (1.f + e);
    return copysignf(t, x);
}
__device__ __forceinline__ ull pack2(float lo, float hi) {
    ull r; asm("mov.b64 %0, {%1,%2};" : "=l"(r) : "f"(lo), "f"(hi)); return r;
}
__device__ __forceinline__ float2 unpack2(ull v) {
    float2 r; asm("mov.b64 {%0,%1}, %2;" : "=f"(r.x), "=f"(r.y) : "l"(v)); return r;
}
__device__ __forceinline__ void ffma2(ull &d, ull a, ull b) {
    asm("fma.rn.f32x2 %0, %1, %2, %0;" : "+l"(d) : "l"(a), "l"(b));
}
__device__ __forceinline__ void barw(int id) {  // warpgroup barrier (128 thr)
    asm volatile("bar.sync %0, 128;" :: "r"(id) : "memory");
}

// ---------------- prologue: transpose LSTM weights ----------------
__global__ void transpose_k(const float* __restrict__ Wih,
                            const float* __restrict__ Whh,
                            const float* __restrict__ Wdh) {
    int i = blockIdx.x * blockDim.x + threadIdx.x;
    if (i < 512 * 128) {
        int o = i >> 7, k = i & 127;
        g_WihT[k * 512 + o]  = Wih[i];
        g_WhhT[k * 512 + o]  = Whh[i];
        g_WhhTd[k * 512 + o] = Wdh[i];
    }
}

// smem float offsets (all multiples of 4)
#define OFF_W      0
#define SZ_W       24704              // 64*386 (enc stride 258, dec 386)
#define OFF_H      (OFF_W + SZ_W)
#define OFF_C      (OFF_H + 1024)
#define OFF_X      (OFF_C + 1024)     // context / proj staging
#define OFF_XD     (OFF_X + 1024)     // x_tilde duplicated [g][2k]
#define OFF_HD     (OFF_XD + 2048)    // h duplicated [g][2k]
#define OFF_BASE   (OFF_HD + 2048)
#define OFF_SC     (OFF_BASE + 512)
#define OFF_GA     (OFF_SC + 512)     // Wih partial (k 0..63)
#define OFF_GB     (OFF_GA + 4096)    // Whh full
#define OFF_GC     (OFF_GB + 4096)    // Wih partial (k 64..127)
#define OFF_BIAS   (OFF_GC + 4096)
#define OFF_WEB    (OFF_BIAS + 512)
#define OFF_WV     (OFF_WEB + 64)     // (w_feat, ve_w) pairs, 128 floats
#define OFF_WDB    (OFF_WV + 128)
#define OFF_VDW    (OFF_WDB + 64)
#define OFF_DWIH   (OFF_VDW + 64)
#define OFF_FCW    (OFF_DWIH + 512)
#define OFF_YH     (OFF_FCW + 320)
#define OFF_YPREV  (OFF_YH + 512)
#define SMEM_FLOATS (OFF_YPREV + 8)
#define SMEM_BYTES  (SMEM_FLOATS * 4)

__global__ void __launch_bounds__(NTHR, 1)
darnn_kernel(const float* __restrict__ X,        const float* __restrict__ y_hist,
             const float* __restrict__ We_w,     const float* __restrict__ We_b,
             const float* __restrict__ ve_w,     const float* __restrict__ ve_b,
             const float* __restrict__ enc_bih,  const float* __restrict__ enc_bhh,
             const float* __restrict__ dec_Wih,  const float* __restrict__ dec_bih,
             const float* __restrict__ dec_bhh,
             const float* __restrict__ Wd_w,     const float* __restrict__ Wd_b,
             const float* __restrict__ vd_w,     const float* __restrict__ vd_b,
             const float* __restrict__ fc_w,     const float* __restrict__ fc_b,
             float* __restrict__ out) {
    extern __shared__ float sm[];
    float* sW      = sm + OFF_W;
    float* s_h     = sm + OFF_H;
    float* s_c     = sm + OFF_C;
    float* s_x     = sm + OFF_X;
    float* s_xd    = sm + OFF_XD;
    float* s_hd    = sm + OFF_HD;
    float* s_base  = sm + OFF_BASE;
    float* s_sc    = sm + OFF_SC;
    float* s_gA    = sm + OFF_GA;
    float* s_gB    = sm + OFF_GB;
    float* s_gC    = sm + OFF_GC;
    float* s_bias  = sm + OFF_BIAS;
    float* s_Web   = sm + OFF_WEB;
    float* s_wv    = sm + OFF_WV;
    float* s_Wdb   = sm + OFF_WDB;
    float* s_vdw   = sm + OFF_VDW;
    float* s_dWih  = sm + OFF_DWIH;
    float* s_fcw   = sm + OFF_FCW;
    float* s_yh    = sm + OFF_YH;
    float* s_yprev = sm + OFF_YPREV;

    const int tid  = threadIdx.x;
    const int lane = tid & 31;
    const int wrp  = tid >> 5;
    const int la   = lane;
    const int b0   = blockIdx.x * G;
    // gemm-warp thread id (warps 8-15)
    const int gt   = tid - 256;
    // phase4 mapping
    const int op4  = tid & 255;
    const int kh4  = tid >> 8;
    // update mapping
    const int gU   = tid >> 6;
    const int i2   = (tid & 63) * 2;
    // proj phase (warpgroup mapping)
    const int gg   = tid >> 7;
    const int wt   = tid & 127;
    const int g0p  = gg * 2, g1p = g0p + 1;
    const int glp  = g0p + (wt >> 6);
    const int a63  = tid & 63;
    const int WB   = 1 + gg;

    const float ve_b_r = ve_b[0];

    // ---------- preload (encoder) ----------
    for (int i = tid; i < 64 * 257; i += NTHR) {
        int r = i / 257, c = i - r * 257;
        sW[r * 258 + c] = We_w[i];
    }
    if (tid < 512) s_bias[tid] = enc_bih[tid] + enc_bhh[tid];
    if (tid < 64) {
        s_Web[tid] = We_b[tid];
        ((float2*)s_wv)[tid] = make_float2(We_w[tid * 257 + 256], ve_w[tid]);
    }
    if (tid < G * Tt) s_yh[tid] = y_hist[b0 * Tt + tid];
    for (int i = tid; i < 1024; i += NTHR) { s_h[i] = 0.f; s_c[i] = 0.f; }
    for (int i = tid; i < 2048; i += NTHR) s_hd[i] = 0.f;
    __syncthreads();

    const ull* WihP  = reinterpret_cast<const ull*>(g_WihT);   // [k][256] o-pairs
    const ull* WhhP  = reinterpret_cast<const ull*>(g_WhhT);
    const ull* WhhPd = reinterpret_cast<const ull*>(g_WhhTd);

    // ================= ENCODER: 64 steps =================
    for (int t = 0; t < Tt; ++t) {
        if (wrp < 8) {
            const int r = wrp;   // batch row
            // ---- E2: base[a] for a = la, la+32 ----
            {
                const ull* Wr0 = (const ull*)(sW + la * 258);
                const ull* Wr1 = (const ull*)(sW + (la + 32) * 258);
                const ull* hg2 = (const ull*)(s_h + r * 128);
                const ull* cg2 = (const ull*)(s_c + r * 128);
                ull a0A = pack2(s_Web[la], 0.f), a0B = 0ULL;
                ull a1A = pack2(s_Web[la + 32], 0.f), a1B = 0ULL;
                #pragma unroll 4
                for (int j = 0; j < 64; j += 2) {
                    ull h0 = hg2[j], h1 = hg2[j + 1];
                    ffma2(a0A, Wr0[j], h0); ffma2(a0B, Wr0[j + 1], h1);
                    ffma2(a1A, Wr1[j], h0); ffma2(a1B, Wr1[j + 1], h1);
                }
                #pragma unroll 4
                for (int j = 0; j < 64; j += 2) {
                    ull c0 = cg2[j], c1 = cg2[j + 1];
                    ffma2(a0A, Wr0[64 + j], c0); ffma2(a0B, Wr0[64 + j + 1], c1);
                    ffma2(a1A, Wr1[64 + j], c0); ffma2(a1B, Wr1[64 + j + 1], c1);
                }
                float2 p = unpack2(a0A), q = unpack2(a0B);
                s_base[r * 64 + la] = (p.x + q.x) + (p.y + q.y);
                p = unpack2(a1A); q = unpack2(a1B);
                s_base[r * 64 + la + 32] = (p.x + q.x) + (p.y + q.y);
            }
            __syncwarp();
            // ---- E3+E4: scores + softmax (warp) + x_tilde ----
            {
                const float* Xg = X + ((size_t)(b0 + r) * Tt + t) * Dd;
                float xv0 = Xg[la], xv1 = Xg[la + 32], xv2 = Xg[la + 64], xv3 = Xg[la + 96];
                float s0 = ve_b_r, s1 = ve_b_r, s2 = ve_b_r, s3 = ve_b_r;
                const float* bg = s_base + r * 64;
                const float2* wv = (const float2*)s_wv;
                #pragma unroll 8
                for (int a = 0; a < 64; ++a) {
                    float ba = bg[a];
                    float2 w = wv[a];   // (w_feat, ve_w)
                    s0 = fmaf(w.y, tanh_fast(fmaf(xv0, w.x, ba)), s0);
                    s1 = fmaf(w.y, tanh_fast(fmaf(xv1, w.x, ba)), s1);
                    s2 = fmaf(w.y, tanh_fast(fmaf(xv2, w.x, ba)), s2);
                    s3 = fmaf(w.y, tanh_fast(fmaf(xv3, w.x, ba)), s3);
                }
                float m = fmaxf(fmaxf(s0, s1), fmaxf(s2, s3));
                #pragma unroll
                for (int o = 16; o; o >>= 1) m = fmaxf(m, __shfl_xor_sync(0xffffffffu, m, o));
                float e0 = __expf(s0 - m), e1 = __expf(s1 - m);
                float e2 = __expf(s2 - m), e3 = __expf(s3 - m);
                float ss = (e0 + e1) + (e2 + e3);
                #pragma unroll
                for (int o = 16; o; o >>= 1) ss += __shfl_xor_sync(0xffffffffu, ss, o);
                float inv = 1.f / ss;
                float v0 = xv0 * e0 * inv, v1 = xv1 * e1 * inv;
                float v2 = xv2 * e2 * inv, v3 = xv3 * e3 * inv;
                float* xd = s_xd + r * 256;
                *(float2*)(xd + 2 * la)        = make_float2(v0, v0);
                *(float2*)(xd + 2 * la + 64)   = make_float2(v1, v1);
                *(float2*)(xd + 2 * la + 128)  = make_float2(v2, v2);
                *(float2*)(xd + 2 * la + 192)  = make_float2(v3, v3);
            }
        } else {
            // ---- Whh · h -> s_gB (full k=128), 256 threads, op = gt ----
            ull acc[8];
            #pragma unroll
            for (int g = 0; g < 8; ++g) acc[g] = 0ULL;
            #pragma unroll 2
            for (int kp = 0; kp < 64; ++kp) {
                ull w0 = WhhP[(2 * kp) * 256 + gt];
                ull w1 = WhhP[(2 * kp + 1) * 256 + gt];
                #pragma unroll
                for (int g = 0; g < 8; ++g) {
                    ulonglong2 hp = *(const ulonglong2*)(s_hd + g * 256 + 4 * kp);
                    ffma2(acc[g], w0, hp.x);
                    ffma2(acc[g], w1, hp.y);
                }
            }
            #pragma unroll
            for (int g = 0; g < 8; ++g) {
                float2 r2 = unpack2(acc[g]);
                *(float2*)(s_gB + g * 512 + 2 * gt) = r2;
            }
        }
        __syncthreads();
        // ---- phase4: Wih · x_tilde, (op4, kh4) split ----
        {
            float* dst = kh4 ? s_gC : s_gA;
            const int kb = kh4 * 64;
            ull acc[8];
            #pragma unroll
            for (int g = 0; g < 8; ++g) acc[g] = 0ULL;
            #pragma unroll 2
            for (int kp = 0; kp < 32; ++kp) {
                int k = kb + 2 * kp;
                ull w0 = WihP[k * 256 + op4];
                ull w1 = WihP[(k + 1) * 256 + op4];
                #pragma unroll
                for (int g = 0; g < 8; ++g) {
                    ulonglong2 xp = *(const ulonglong2*)(s_xd + g * 256 + 2 * k);
                    ffma2(acc[g], w0, xp.x);
                    ffma2(acc[g], w1, xp.y);
                }
            }
            #pragma unroll
            for (int g = 0; g < 8; ++g) {
                float2 r2 = unpack2(acc[g]);
                *(float2*)(dst + g * 512 + 2 * op4) = r2;
            }
        }
        __syncthreads();
        // ---- E6: LSTM update, 2 units per thread ----
        {
            const float2* gA2 = (const float2*)(s_gA + gU * 512);
            const float2* gB2 = (const float2*)(s_gB + gU * 512);
            const float2* gC2 = (const float2*)(s_gC + gU * 512);
            const float2* b2  = (const float2*)s_bias;
            const int h2i = i2 >> 1;
            float pre[4][2];
            #pragma unroll
            for (int q = 0; q < 4; ++q) {
                int idx = q * 64 + h2i;
                float2 vA = gA2[idx], vB = gB2[idx], vC = gC2[idx], vb = b2[idx];
                pre[q][0] = ((vA.x + vB.x) + (vC.x + vb.x));
                pre[q][1] = ((vA.y + vB.y) + (vC.y + vb.y));
            }
            float hh[2];
            #pragma unroll
            for (int j = 0; j < 2; ++j) {
                float ig = sigm(pre[0][j]);
                float fg = sigm(pre[1][j]);
                float gv = tanh_acc(pre[2][j]);
                float og = sigm(pre[3][j]);
                float c2 = fmaf(fg, s_c[gU * 128 + i2 + j], ig * gv);
                float h2 = og * tanh_acc(c2);
                s_c[gU * 128 + i2 + j] = c2;
                s_h[gU * 128 + i2 + j] = h2;
                hh[j] = h2;
            }
            *(float4*)(s_hd + gU * 256 + 2 * i2) = make_float4(hh[0], hh[0], hh[1], hh[1]);
            *(float2*)(g_hid + ((size_t)(b0 + gU) * Tt + t) * Hh + i2) = make_float2(hh[0], hh[1]);
        }
        __syncthreads();
    }

    // ================= enc_proj =================
    for (int i = tid; i < 64 * 384; i += NTHR) {
        int r = i / 384, c = i - r * 384;
        sW[r * 386 + c] = Wd_w[i];
    }
    __syncthreads();
    for (int t = 0; t < Tt; ++t) {
        s_x[g0p * 128 + wt] = g_hid[((size_t)(b0 + g0p) * Tt + t) * Hh + wt];
        s_x[g1p * 128 + wt] = g_hid[((size_t)(b0 + g1p) * Tt + t) * Hh + wt];
        barw(WB);
        {
            const ull* Wr2 = (const ull*)(sW + a63 * 386);
            const ull* hg2 = (const ull*)(s_x + glp * 128);
            ull aA = 0ULL, aB = 0ULL;
            #pragma unroll 8
            for (int j = 0; j < 64; j += 2) {
                ffma2(aA, Wr2[j], hg2[j]);
                ffma2(aB, Wr2[j + 1], hg2[j + 1]);
            }
            float2 ra = unpack2(aA), rb = unpack2(aB);
            g_proj[((size_t)(b0 + glp)) * ATT * Tt + a63 * Tt + t] = (ra.x + rb.x) + (ra.y + rb.y);
        }
        barw(WB);
    }

    // ---------- preload (decoder) ----------
    __syncthreads();
    if (tid < 512) {
        s_bias[tid] = dec_bih[tid] + dec_bhh[tid];
        s_dWih[tid] = dec_Wih[tid];
    }
    if (tid < 64) { s_Wdb[tid] = Wd_b[tid]; s_vdw[tid] = vd_w[tid]; }
    if (tid < 320) s_fcw[tid] = fc_w[tid];
    for (int i = tid; i < 1024; i += NTHR) { s_h[i] = 0.f; s_c[i] = 0.f; }
    for (int i = tid; i < 2048; i += NTHR) s_hd[i] = 0.f;
    if (tid < G) s_yprev[tid] = s_yh[tid * Tt + Tt - 1];
    const float vd_b_r = vd_b[0];
    const float fc_b_r = fc_b[0];
    __syncthreads();

    // D7 helper
    auto do_D7 = [&](int s) {
        const int r = wrp;
        float acc = 0.f;
        #pragma unroll
        for (int it = 0; it < 10; ++it) {
            int idx = lane + it * 32;
            float v;
            if (idx < 128)      v = s_h[r * 128 + idx];
            else if (idx < 256) v = s_x[r * 128 + idx - 128];
            else                v = s_yh[r * 64 + idx - 256];
            acc = fmaf(s_fcw[idx], v, acc);
        }
        #pragma unroll
        for (int o = 16; o; o >>= 1) acc += __shfl_xor_sync(0xffffffffu, acc, o);
        if (lane == 0) {
            float ov = acc + fc_b_r;
            s_yprev[r] = ov;
            out[(b0 + r) * HOR + s] = ov;
        }
    };

    // ================= DECODER: 24 steps =================
    for (int s = 0; s < HOR; ++s) {
        if (wrp < 8) {
            const int r = wrp;
            if (s > 0) do_D7(s - 1);
            // ---- D1: dc[a] for a = la, la+32 ----
            {
                const ull* W0d = (const ull*)(sW + la * 386 + 128);
                const ull* W0c = (const ull*)(sW + la * 386 + 256);
                const ull* W1d = (const ull*)(sW + (la + 32) * 386 + 128);
                const ull* W1c = (const ull*)(sW + (la + 32) * 386 + 256);
                const ull* dg2 = (const ull*)(s_h + r * 128);
                const ull* cg2 = (const ull*)(s_c + r * 128);
                ull a0A = pack2(s_Wdb[la], 0.f), a0B = 0ULL;
                ull a1A = pack2(s_Wdb[la + 32], 0.f), a1B = 0ULL;
                #pragma unroll 4
                for (int j = 0; j < 64; j += 2) {
                    ull d0 = dg2[j], d1 = dg2[j + 1];
                    ffma2(a0A, W0d[j], d0); ffma2(a0B, W0d[j + 1], d1);
                    ffma2(a1A, W1d[j], d0); ffma2(a1B, W1d[j + 1], d1);
                }
                #pragma unroll 4
                for (int j = 0; j < 64; j += 2) {
                    ull c0 = cg2[j], c1 = cg2[j + 1];
                    ffma2(a0A, W0c[j], c0); ffma2(a0B, W0c[j + 1], c1);
                    ffma2(a1A, W1c[j], c0); ffma2(a1B, W1c[j + 1], c1);
                }
                float2 p = unpack2(a0A), q = unpack2(a0B);
                s_base[r * 64 + la] = (p.x + q.x) + (p.y + q.y);
                p = unpack2(a1A); q = unpack2(a1B);
                s_base[r * 64 + la + 32] = (p.x + q.x) + (p.y + q.y);
            }
            __syncwarp();
            // ---- D2+D3: scores over t + softmax (warp) -> beta ----
            {
                const float* pp = g_proj + ((size_t)(b0 + r)) * ATT * Tt;
                const float* bg = s_base + r * 64;
                float ac0 = vd_b_r, ac1 = vd_b_r;
                #pragma unroll 4
                for (int a = 0; a < 64; ++a) {
                    float dca = bg[a];
                    float vw = s_vdw[a];
                    float p0 = pp[a * 64 + la];
                    float p1 = pp[a * 64 + la + 32];
                    ac0 = fmaf(vw, tanh_fast(p0 + dca), ac0);
                    ac1 = fmaf(vw, tanh_fast(p1 + dca), ac1);
                }
                float m = fmaxf(ac0, ac1);
                #pragma unroll
                for (int o = 16; o; o >>= 1) m = fmaxf(m, __shfl_xor_sync(0xffffffffu, m, o));
                float e0 = __expf(ac0 - m), e1 = __expf(ac1 - m);
                float ss = e0 + e1;
                #pragma unroll
                for (int o = 16; o; o >>= 1) ss += __shfl_xor_sync(0xffffffffu, ss, o);
                float inv = 1.f / ss;
                s_sc[r * 64 + la]      = e0 * inv;
                s_sc[r * 64 + la + 32] = e1 * inv;
            }
            __syncwarp();
            // ---- D4: context -> s_x (4 units per lane, float4) ----
            {
                const int u4 = 4 * la;
                const float4* hp4 = (const float4*)(g_hid + ((size_t)(b0 + r) * Tt) * Hh + u4);
                const float* be = s_sc + r * 64;
                float4 acc = make_float4(0.f, 0.f, 0.f, 0.f);
                #pragma unroll 4
                for (int tt = 0; tt < 64; ++tt) {
                    float b = be[tt];
                    float4 hv = hp4[tt * 32];
                    acc.x = fmaf(b, hv.x, acc.x);
                    acc.y = fmaf(b, hv.y, acc.y);
                    acc.z = fmaf(b, hv.z, acc.z);
                    acc.w = fmaf(b, hv.w, acc.w);
                }
                *(float4*)(s_x + r * 128 + u4) = acc;
            }
        } else {
            // ---- D5: Whh_dec · h -> s_gB (full k=128) ----
            ull acc[8];
            #pragma unroll
            for (int g = 0; g < 8; ++g) acc[g] = 0ULL;
            #pragma unroll 2
            for (int kp = 0; kp < 64; ++kp) {
                ull w0 = WhhPd[(2 * kp) * 256 + gt];
                ull w1 = WhhPd[(2 * kp + 1) * 256 + gt];
                #pragma unroll
                for (int g = 0; g < 8; ++g) {
                    ulonglong2 hp = *(const ulonglong2*)(s_hd + g * 256 + 4 * kp);
                    ffma2(acc[g], w0, hp.x);
                    ffma2(acc[g], w1, hp.y);
                }
            }
            #pragma unroll
            for (int g = 0; g < 8; ++g) {
                float2 r2 = unpack2(acc[g]);
                *(float2*)(s_gB + g * 512 + 2 * gt) = r2;
            }
        }
        __syncthreads();
        // ---- D6: LSTM update (gB + bias + dWih*y_prev) ----
        {
            const float2* gB2 = (const float2*)(s_gB + gU * 512);
            const float2* b2  = (const float2*)s_bias;
            const float2* w2p = (const float2*)s_dWih;
            const int h2i = i2 >> 1;
            float y = s_yprev[gU];
            float pre[4][2];
            #pragma unroll
            for (int q = 0; q < 4; ++q) {
                int idx = q * 64 + h2i;
                float2 vB = gB2[idx], vb = b2[idx], vw = w2p[idx];
                pre[q][0] = fmaf(vw.x, y, vB.x + vb.x);
                pre[q][1] = fmaf(vw.y, y, vB.y + vb.y);
            }
            float hh[2];
            #pragma unroll
            for (int j = 0; j < 2; ++j) {
                float ig = sigm(pre[0][j]);
                float fg = sigm(pre[1][j]);
                float gv = tanh_acc(pre[2][j]);
                float og = sigm(pre[3][j]);
                float c2 = fmaf(fg, s_c[gU * 128 + i2 + j], ig * gv);
                float h2 = og * tanh_acc(c2);
                s_c[gU * 128 + i2 + j] = c2;
                s_h[gU * 128 + i2 + j] = h2;
                hh[j] = h2;
            }
            *(float4*)(s_hd + gU * 256 + 2 * i2) = make_float4(hh[0], hh[0], hh[1], hh[1]);
        }
        __syncthreads();
    }
    // final output step
    if (wrp < 8) do_D7(HOR - 1);
}

extern "C" void kernel_launch(void* const* d_in, const int* in_sizes, int n_in,
                              void* d_out, int out_size) {
    const float* X        = (const float*)d_in[0];
    const float* y_hist   = (const float*)d_in[1];
    const float* We_w     = (const float*)d_in[2];
    const float* We_b     = (const float*)d_in[3];
    const float* ve_w     = (const float*)d_in[4];
    const float* ve_b     = (const float*)d_in[5];
    const float* enc_Wih  = (const float*)d_in[6];
    const float* enc_Whh  = (const float*)d_in[7];
    const float* enc_bih  = (const float*)d_in[8];
    const float* enc_bhh  = (const float*)d_in[9];
    const float* dec_Wih  = (const float*)d_in[10];
    const float* dec_Whh  = (const float*)d_in[11];
    const float* dec_bih  = (const float*)d_in[12];
    const float* dec_bhh  = (const float*)d_in[13];
    const float* Wd_w     = (const float*)d_in[14];
    const float* Wd_b     = (const float*)d_in[15];
    const float* vd_w     = (const float*)d_in[16];
    const float* vd_b     = (const float*)d_in[17];
    const float* fc_w     = (const float*)d_in[18];
    const float* fc_b     = (const float*)d_in[19];
    float* out = (float*)d_out;

    cudaFuncSetAttribute(darnn_kernel,
                         cudaFuncAttributeMaxDynamicSharedMemorySize, SMEM_BYTES);

    transpose_k<<<(512 * 128 + 255) / 256, 256>>>(enc_Wih, enc_Whh, dec_Whh);
    darnn_kernel<<<NCTAS, NTHR, SMEM_BYTES>>>(
        X, y_hist, We_w, We_b, ve_w, ve_b,
        enc_bih, enc_bhh, dec_Wih, dec_bih, dec_bhh,
        Wd_w, Wd_b, vd_w, vd_b, fc_w, fc_b, out);
}